// round 8
// baseline (speedup 1.0000x reference)
#include <cuda_runtime.h>
#include <cstdint>

// CRPS loss — cp.async double-buffered smem staging + packed f32x2 compute.
//   term1 = mean_i |s_i - y| ; term2 = sum_{i<j}|s_i - s_j| / 256
//   out   = mean_pixels (term1 - term2)
//
// samples: [16, 4, 1, 256, 256] f32 -> 16 planes of 262144 floats
// target:  [4, 1, 256, 256]     f32 -> 262144 floats
//
// 512 CTAs x 128 threads. CTA owns 512 pixels, split into 2 chunks of 256.
// All bytes staged via cp.async (no MLP/register coupling), chunk1 DMA
// overlaps chunk0 compute. Compute math identical to previous round.

#define NS        16
#define NPIX      (4 * 1 * 256 * 256)   // 262144
#define THREADS   128
#define BLOCKS    512
#define PIX_CTA   512                   // pixels per CTA
#define CHUNK_PIX 256                   // pixels per chunk
#define PLANE_B   (CHUNK_PIX * 4)       // 1024 bytes per plane per chunk
#define CHUNK_B   ((NS + 1) * PLANE_B)  // 17408 bytes (16 planes + target)
#define OPS_CHUNK ((NS + 1) * (PLANE_B / 16))   // 1088 x 16B cp.async ops

__device__ float        g_partial[BLOCKS];
__device__ unsigned int g_done = 0;

// ---- packed f32x2 helpers (sm_103a) ----
__device__ __forceinline__ uint64_t fadd2(uint64_t a, uint64_t b) {
    uint64_t r; asm("add.rn.f32x2 %0, %1, %2;" : "=l"(r) : "l"(a), "l"(b)); return r;
}
__device__ __forceinline__ uint64_t ffma2(uint64_t a, uint64_t b, uint64_t c) {
    uint64_t r; asm("fma.rn.f32x2 %0, %1, %2, %3;" : "=l"(r) : "l"(a), "l"(b), "l"(c)); return r;
}
__device__ __forceinline__ uint64_t fabs2(uint64_t a) {
    return a & 0x7FFFFFFF7FFFFFFFULL;
}
__device__ __forceinline__ float2 unpack2(uint64_t v) {
    float lo, hi; asm("mov.b64 {%0, %1}, %2;" : "=f"(lo), "=f"(hi) : "l"(v));
    return make_float2(lo, hi);
}
#define NEG_ONE2 0xBF800000BF800000ULL

__device__ __forceinline__ uint32_t smem_u32(const void* p) {
    uint32_t a;
    asm("{ .reg .u64 t; cvta.to.shared.u64 t, %1; cvt.u32.u64 %0, t; }"
        : "=r"(a) : "l"(p));
    return a;
}
__device__ __forceinline__ void cp_async16(uint32_t dst, const void* src) {
    asm volatile("cp.async.cg.shared.global [%0], [%1], 16;"
                 :: "r"(dst), "l"(src));
}

__global__ __launch_bounds__(THREADS) void crps_fused_kernel(
    const float* __restrict__ samples,
    const float* __restrict__ target,
    float* __restrict__ out)
{
    __shared__ alignas(16) char sm[2][CHUNK_B];     // 34816 B

    const int tid  = threadIdx.x;
    const int base = blockIdx.x * PIX_CTA;          // first pixel of this CTA
    const uint32_t smb = smem_u32(&sm[0][0]);

    // ---- issue both chunks' DMA up front (fire-and-forget, full MLP) ----
#pragma unroll
    for (int c = 0; c < 2; c++) {
        const int pbase = base + c * CHUNK_PIX;
#pragma unroll 1
        for (int idx = tid; idx < OPS_CHUNK; idx += THREADS) {
            const int plane = idx >> 6;             // 0..16 (16 = target)
            const int pos   = idx & 63;             // 16B unit within plane
            const float* src = (plane < NS)
                ? samples + (size_t)plane * NPIX + pbase + pos * 4
                : target + pbase + pos * 4;
            cp_async16(smb + c * CHUNK_B + plane * PLANE_B + pos * 16, src);
        }
        asm volatile("cp.async.commit_group;" ::: "memory");
    }

    // ---- compute both chunks, overlapping chunk1 DMA with chunk0 math ----
    float val = 0.0f;
#pragma unroll
    for (int c = 0; c < 2; c++) {
        if (c == 0) asm volatile("cp.async.wait_group 1;" ::: "memory");
        else        asm volatile("cp.async.wait_group 0;" ::: "memory");
        __syncthreads();

        // thread's float2 group within chunk: pixels [2*tid, 2*tid+1]
        uint64_t s[NS];
#pragma unroll
        for (int i = 0; i < NS; i++)
            s[i] = reinterpret_cast<const uint64_t*>(sm[c] + i * PLANE_B)[tid];
        const uint64_t y =
            reinterpret_cast<const uint64_t*>(sm[c] + NS * PLANE_B)[tid];

        uint64_t t1a = 0, t1b = 0;
#pragma unroll
        for (int i = 0; i < NS; i += 2) {
            t1a = fadd2(t1a, fabs2(ffma2(y, NEG_ONE2, s[i])));
            t1b = fadd2(t1b, fabs2(ffma2(y, NEG_ONE2, s[i + 1])));
        }

        uint64_t t2[4] = {0, 0, 0, 0};
        {
            int cc = 0;
#pragma unroll
            for (int i = 0; i < NS; i++) {
#pragma unroll
                for (int j = i + 1; j < NS; j++) {
                    t2[cc & 3] = fadd2(t2[cc & 3],
                                       fabs2(ffma2(s[j], NEG_ONE2, s[i])));
                    cc++;
                }
            }
        }

        const float2 p1 = unpack2(fadd2(t1a, t1b));
        const float2 p2 = unpack2(fadd2(fadd2(t2[0], t2[1]), fadd2(t2[2], t2[3])));
        val += (p1.x + p1.y) * (1.0f / NS)
             - (p2.x + p2.y) * (1.0f / (NS * NS));
    }

    // ---- block reduction (4 warps) ----
    __shared__ float warp_sum[THREADS / 32];
    float w = val;
#pragma unroll
    for (int off = 16; off > 0; off >>= 1)
        w += __shfl_down_sync(0xFFFFFFFFu, w, off);
    if ((tid & 31) == 0) warp_sum[tid >> 5] = w;
    __syncthreads();

    __shared__ bool is_last;
    if (tid == 0) {
        float b = (warp_sum[0] + warp_sum[1]) + (warp_sum[2] + warp_sum[3]);
        g_partial[blockIdx.x] = b;
        __threadfence();
        unsigned int ticket = atomicAdd(&g_done, 1u);
        is_last = (ticket == BLOCKS - 1);
    }
    __syncthreads();

    if (is_last) {
        float acc = 0.0f;
#pragma unroll
        for (int k = 0; k < BLOCKS / THREADS; k++)
            acc += g_partial[tid + k * THREADS];
#pragma unroll
        for (int off = 16; off > 0; off >>= 1)
            acc += __shfl_down_sync(0xFFFFFFFFu, acc, off);
        if ((tid & 31) == 0) warp_sum[tid >> 5] = acc;
        __syncthreads();
        if (tid == 0) {
            float total = (warp_sum[0] + warp_sum[1]) + (warp_sum[2] + warp_sum[3]);
            out[0] = total * (1.0f / NPIX);
            g_done = 0;                 // reset for next graph replay
        }
    }
}

extern "C" void kernel_launch(void* const* d_in, const int* in_sizes, int n_in,
                              void* d_out, int out_size)
{
    const float* samples = (const float*)d_in[0];
    const float* target  = (const float*)d_in[1];
    crps_fused_kernel<<<BLOCKS, THREADS>>>(samples, target, (float*)d_out);
}